// round 8
// baseline (speedup 1.0000x reference)
#include <cuda_runtime.h>
#include <cuda_fp16.h>
#include <cstdint>

#define DIMD 1024
#define NB   8
#define SQ   2048
#define SKV  2048

// ---- scratch (device globals; no allocation allowed) ----
__device__ __half g_Xh[(size_t)NB * SQ * DIMD];
__device__ __half g_Ch[(size_t)NB * SKV * DIMD];
__device__ __half g_Wqh[DIMD * DIMD];
__device__ __half g_Wkh[DIMD * DIMD];
__device__ __half g_Wvh[DIMD * DIMD];
__device__ __half g_Qh[(size_t)NB * SQ * DIMD];
__device__ __half g_Kh[(size_t)NB * SKV * DIMD];
__device__ __half g_Vth[(size_t)NB * DIMD * SKV];   // [b][e][t]
__device__ float  g_S[(size_t)NB * SQ * SKV];
__device__ __half g_P[(size_t)NB * SQ * SKV];

// ---- fp32 -> fp16 conversion ----
__global__ void cvt_h_kernel(const float4* __restrict__ in, __half2* __restrict__ out, int n4) {
    int i = blockIdx.x * blockDim.x + threadIdx.x;
    int stride = gridDim.x * blockDim.x;
    for (; i < n4; i += stride) {
        float4 v = in[i];
        out[2 * i]     = __floats2half2_rn(v.x, v.y);
        out[2 * i + 1] = __floats2half2_rn(v.z, v.w);
    }
}

// ================ fp16 TN GEMM: C[M,N] = alpha * A[M,K] * B[N,K]^T ================
// Tile 128(M) x 256(N), BK=32 halves, 3-stage cp.async (1 syncthreads/iter),
// warp tile 64x64, mma.m16n8k16, B frags via ldmatrix.x4 (2 n-tiles per instr).
#define BM 128
#define BN 256
#define BKH 32                 // halves per k-stage
#define RSTRB 80               // bytes per smem row (64 data + 16 pad)
#define ASZB (BM * RSTRB)      // 10240
#define BSZB (BN * RSTRB)      // 20480
#define STG  (ASZB + BSZB)     // 30720 per stage
#define NST 3
#define SMEMB (NST * STG)      // 92160

__device__ __forceinline__ void cpa16(uint32_t s, const void* g) {
    asm volatile("cp.async.cg.shared.global [%0], [%1], 16;" :: "r"(s), "l"(g));
}

// MODE 0: fp32 store; MODE 1: fp16 store; MODE 2: fp16 transposed store C[n*ldc+m]
template<int MODE>
__global__ __launch_bounds__(256)
void gemm_h(const __half* __restrict__ Ag, const __half* __restrict__ Bg, void* __restrict__ Cv,
            int K, long sA, long sB, long sC, int ldc, float alpha)
{
    extern __shared__ __align__(16) char dsm[];
    const int tid = threadIdx.x, lane = tid & 31, warp = tid >> 5;
    const int m0 = blockIdx.y * BM, n0 = blockIdx.x * BN;
    const __half* A = Ag + (long)blockIdx.z * sA;
    const __half* B = Bg + (long)blockIdx.z * sB;
    const int wm = (warp & 1) * 64, wn = (warp >> 1) * 64;

    uint32_t sb = (uint32_t)__cvta_generic_to_shared(dsm);

    // producers: thread t -> one primary 64B row; threads <128 also one secondary B row
    const __half* g0 = (tid < 128) ? (A + (long)(m0 + tid) * K)
                                   : (B + (long)(n0 + tid - 128) * K);
    const uint32_t s0 = (tid < 128) ? (uint32_t)tid * RSTRB
                                    : (uint32_t)(ASZB + (tid - 128) * RSTRB);
    const __half* g1 = B + (long)(n0 + 128 + tid) * K;     // valid only tid<128
    const uint32_t s1 = (uint32_t)(ASZB + (128 + tid) * RSTRB);

    float acc[4][8][4];
    #pragma unroll
    for (int i = 0; i < 4; i++)
        #pragma unroll
        for (int j = 0; j < 8; j++)
            #pragma unroll
            for (int r = 0; r < 4; r++) acc[i][j][r] = 0.f;

    auto issue = [&](int kt, int slot) {
        uint32_t off = sb + (uint32_t)slot * STG;
        const __half* p0 = g0 + kt * BKH;
        #pragma unroll
        for (int c = 0; c < 4; ++c) cpa16(off + s0 + c * 16u, p0 + c * 8);
        if (tid < 128) {
            const __half* p1 = g1 + kt * BKH;
            #pragma unroll
            for (int c = 0; c < 4; ++c) cpa16(off + s1 + c * 16u, p1 + c * 8);
        }
        asm volatile("cp.async.commit_group;");
    };

    // fragment lane addressing (identical recipe for A and B x4 loads)
    const uint32_t aoff = (uint32_t)((wm + (lane & 15)) * RSTRB + ((lane >> 4) & 1) * 16);
    const uint32_t boff = (uint32_t)(ASZB + (wn + (lane & 15)) * RSTRB + ((lane >> 4) & 1) * 16);

    const int KT = K >> 5;
    issue(0, 0);
    issue(1, 1);

    for (int kt = 0; kt < KT; ++kt) {
        asm volatile("cp.async.wait_group 1;");
        __syncthreads();
        if (kt + 2 < KT) issue(kt + 2, (kt + 2) % NST);
        uint32_t stg = sb + (uint32_t)(kt % NST) * STG;
        #pragma unroll
        for (int ks = 0; ks < 2; ++ks) {
            uint32_t a[4][4], b[4][4];
            #pragma unroll
            for (int mt = 0; mt < 4; mt++) {
                uint32_t ad = stg + aoff + (uint32_t)(mt * 16 * RSTRB + ks * 32);
                asm volatile("ldmatrix.sync.aligned.m8n8.x4.shared.b16 {%0,%1,%2,%3}, [%4];"
                    : "=r"(a[mt][0]), "=r"(a[mt][1]), "=r"(a[mt][2]), "=r"(a[mt][3]) : "r"(ad));
            }
            #pragma unroll
            for (int p = 0; p < 4; p++) {
                uint32_t bd = stg + boff + (uint32_t)(p * 16 * RSTRB + ks * 32);
                asm volatile("ldmatrix.sync.aligned.m8n8.x4.shared.b16 {%0,%1,%2,%3}, [%4];"
                    : "=r"(b[p][0]), "=r"(b[p][1]), "=r"(b[p][2]), "=r"(b[p][3]) : "r"(bd));
            }
            #pragma unroll
            for (int mt = 0; mt < 4; mt++)
                #pragma unroll
                for (int p = 0; p < 4; p++) {
                    // n-tile 2p: rows p*16+0..7 -> {b[p][0], b[p][2]}
                    asm volatile("mma.sync.aligned.m16n8k16.row.col.f32.f16.f16.f32 "
                        "{%0,%1,%2,%3}, {%4,%5,%6,%7}, {%8,%9}, {%0,%1,%2,%3};"
                        : "+f"(acc[mt][2*p][0]), "+f"(acc[mt][2*p][1]),
                          "+f"(acc[mt][2*p][2]), "+f"(acc[mt][2*p][3])
                        : "r"(a[mt][0]), "r"(a[mt][1]), "r"(a[mt][2]), "r"(a[mt][3]),
                          "r"(b[p][0]), "r"(b[p][2]));
                    // n-tile 2p+1: rows p*16+8..15 -> {b[p][1], b[p][3]}
                    asm volatile("mma.sync.aligned.m16n8k16.row.col.f32.f16.f16.f32 "
                        "{%0,%1,%2,%3}, {%4,%5,%6,%7}, {%8,%9}, {%0,%1,%2,%3};"
                        : "+f"(acc[mt][2*p+1][0]), "+f"(acc[mt][2*p+1][1]),
                          "+f"(acc[mt][2*p+1][2]), "+f"(acc[mt][2*p+1][3])
                        : "r"(a[mt][0]), "r"(a[mt][1]), "r"(a[mt][2]), "r"(a[mt][3]),
                          "r"(b[p][1]), "r"(b[p][3]));
                }
        }
    }

    // ---- epilogue ----
    const int rr = lane >> 2, cc = (lane & 3) * 2;
    #pragma unroll
    for (int mt = 0; mt < 4; mt++) {
        #pragma unroll
        for (int nt = 0; nt < 8; nt++) {
            int row = m0 + wm + mt * 16 + rr;
            int col = n0 + wn + nt * 8 + cc;
            float v0 = acc[mt][nt][0] * alpha, v1 = acc[mt][nt][1] * alpha;
            float v2 = acc[mt][nt][2] * alpha, v3 = acc[mt][nt][3] * alpha;
            if (MODE == 0) {
                float* C = (float*)Cv + (long)blockIdx.z * sC;
                *reinterpret_cast<float2*>(&C[(long)row       * ldc + col]) = make_float2(v0, v1);
                *reinterpret_cast<float2*>(&C[(long)(row + 8) * ldc + col]) = make_float2(v2, v3);
            } else if (MODE == 1) {
                __half* C = (__half*)Cv + (long)blockIdx.z * sC;
                *reinterpret_cast<__half2*>(&C[(long)row       * ldc + col]) = __floats2half2_rn(v0, v1);
                *reinterpret_cast<__half2*>(&C[(long)(row + 8) * ldc + col]) = __floats2half2_rn(v2, v3);
            } else {
                __half* C = (__half*)Cv + (long)blockIdx.z * sC;
                C[(long)col       * ldc + row    ] = __float2half_rn(v0);
                C[(long)(col + 1) * ldc + row    ] = __float2half_rn(v1);
                C[(long)col       * ldc + row + 8] = __float2half_rn(v2);
                C[(long)(col + 1) * ldc + row + 8] = __float2half_rn(v3);
            }
        }
    }
}

// ---- row softmax over 2048 fp32 cols -> fp16 P ----
__global__ void softmax_kernel(const float* __restrict__ S, __half* __restrict__ P) {
    const float* p = S + (long)blockIdx.x * SKV;
    __half* q = P + (long)blockIdx.x * SKV;
    const int tid = threadIdx.x;  // 256
    float v[8];
    float mx = -3.4e38f;
    #pragma unroll
    for (int i = 0; i < 8; i++) { v[i] = p[tid + (i << 8)]; mx = fmaxf(mx, v[i]); }
    #pragma unroll
    for (int o = 16; o; o >>= 1) mx = fmaxf(mx, __shfl_xor_sync(0xffffffffu, mx, o));
    __shared__ float red[8];
    if ((tid & 31) == 0) red[tid >> 5] = mx;
    __syncthreads();
    float m = red[0];
    #pragma unroll
    for (int i = 1; i < 8; i++) m = fmaxf(m, red[i]);
    float s = 0.f;
    #pragma unroll
    for (int i = 0; i < 8; i++) { v[i] = __expf(v[i] - m); s += v[i]; }
    #pragma unroll
    for (int o = 16; o; o >>= 1) s += __shfl_xor_sync(0xffffffffu, s, o);
    __syncthreads();
    if ((tid & 31) == 0) red[tid >> 5] = s;
    __syncthreads();
    float tot = 0.f;
    #pragma unroll
    for (int i = 0; i < 8; i++) tot += red[i];
    float inv = 1.0f / tot;
    #pragma unroll
    for (int i = 0; i < 8; i++) q[tid + (i << 8)] = __float2half_rn(v[i] * inv);
}

extern "C" void kernel_launch(void* const* d_in, const int* in_sizes, int n_in,
                              void* d_out, int out_size) {
    const float* x  = (const float*)d_in[0];
    const float* cx = (const float*)d_in[1];
    const float* wq = (const float*)d_in[2];
    const float* wk = (const float*)d_in[3];
    const float* wv = (const float*)d_in[4];
    float* out = (float*)d_out;

    __half *pXh, *pCh, *pWq, *pWk, *pWv, *pQ, *pK, *pVt, *pP;
    float *pS;
    cudaGetSymbolAddress((void**)&pXh, g_Xh);
    cudaGetSymbolAddress((void**)&pCh, g_Ch);
    cudaGetSymbolAddress((void**)&pWq, g_Wqh);
    cudaGetSymbolAddress((void**)&pWk, g_Wkh);
    cudaGetSymbolAddress((void**)&pWv, g_Wvh);
    cudaGetSymbolAddress((void**)&pQ,  g_Qh);
    cudaGetSymbolAddress((void**)&pK,  g_Kh);
    cudaGetSymbolAddress((void**)&pVt, g_Vth);
    cudaGetSymbolAddress((void**)&pS,  g_S);
    cudaGetSymbolAddress((void**)&pP,  g_P);

    cudaFuncSetAttribute(gemm_h<0>, cudaFuncAttributeMaxDynamicSharedMemorySize, SMEMB);
    cudaFuncSetAttribute(gemm_h<1>, cudaFuncAttributeMaxDynamicSharedMemorySize, SMEMB);
    cudaFuncSetAttribute(gemm_h<2>, cudaFuncAttributeMaxDynamicSharedMemorySize, SMEMB);

    // 1) convert inputs to fp16
    cvt_h_kernel<<<2048, 256>>>((const float4*)x,  (__half2*)pXh, NB * SQ * DIMD / 4);
    cvt_h_kernel<<<2048, 256>>>((const float4*)cx, (__half2*)pCh, NB * SKV * DIMD / 4);
    cvt_h_kernel<<<512,  256>>>((const float4*)wq, (__half2*)pWq, DIMD * DIMD / 4);
    cvt_h_kernel<<<512,  256>>>((const float4*)wk, (__half2*)pWk, DIMD * DIMD / 4);
    cvt_h_kernel<<<512,  256>>>((const float4*)wv, (__half2*)pWv, DIMD * DIMD / 4);

    dim3 blk(256);
    // 2) Q = X Wq^T (fp16 store)
    gemm_h<1><<<dim3(DIMD / BN, NB * SQ / BM, 1), blk, SMEMB>>>(
        pXh, pWq, pQ, DIMD, 0, 0, 0, DIMD, 1.f);
    // 3) K = C Wk^T
    gemm_h<1><<<dim3(DIMD / BN, NB * SKV / BM, 1), blk, SMEMB>>>(
        pCh, pWk, pK, DIMD, 0, 0, 0, DIMD, 1.f);
    // 4) Vt[b][e][t] = (C Wv^T)^T  (fp16 transposed store)
    gemm_h<2><<<dim3(DIMD / BN, SKV / BM, NB), blk, SMEMB>>>(
        pCh, pWv, pVt, DIMD, (long)SKV * DIMD, 0, (long)DIMD * SKV, SKV, 1.f);
    // 5) S[b] = Q[b] K[b]^T * D^-0.5  (fp32 store)
    gemm_h<0><<<dim3(SKV / BN, SQ / BM, NB), blk, SMEMB>>>(
        pQ, pK, pS, DIMD, (long)SQ * DIMD, (long)SKV * DIMD, (long)SQ * SKV, SKV, 0.03125f);
    // 6) P = softmax(S)  (fp32 -> fp16)
    softmax_kernel<<<NB * SQ, 256>>>(pS, pP);
    // 7) O[b] = P[b] Vt[b]^T  -> d_out (fp32)
    gemm_h<0><<<dim3(DIMD / BN, SQ / BM, NB), blk, SMEMB>>>(
        pP, pVt, out, SKV, (long)SQ * SKV, (long)DIMD * SKV, (long)SQ * DIMD, DIMD, 1.f);
}

// round 9
// speedup vs baseline: 1.4763x; 1.4763x over previous
#include <cuda_runtime.h>
#include <cuda_fp16.h>
#include <cstdint>

#define DIMD 1024
#define NB   8
#define SQ   2048
#define SKV  2048

// ---- scratch (device globals; no allocation allowed) ----
__device__ __half g_Xh[(size_t)NB * SQ * DIMD];
__device__ __half g_Ch[(size_t)NB * SKV * DIMD];
__device__ __half g_Wqh[DIMD * DIMD];
__device__ __half g_Wkh[DIMD * DIMD];
__device__ __half g_Wvh[DIMD * DIMD];
__device__ __half g_Qh[(size_t)NB * SQ * DIMD];
__device__ __half g_Kh[(size_t)NB * SKV * DIMD];
__device__ __half g_Vth[(size_t)NB * DIMD * SKV];   // [b][e][t]
__device__ float  g_S[(size_t)NB * SQ * SKV];
__device__ __half g_P[(size_t)NB * SQ * SKV];

// ---- fp32 -> fp16 conversion ----
__global__ void cvt_h_kernel(const float4* __restrict__ in, __half2* __restrict__ out, int n4) {
    int i = blockIdx.x * blockDim.x + threadIdx.x;
    int stride = gridDim.x * blockDim.x;
    for (; i < n4; i += stride) {
        float4 v = in[i];
        out[2 * i]     = __floats2half2_rn(v.x, v.y);
        out[2 * i + 1] = __floats2half2_rn(v.z, v.w);
    }
}

// ================ fp16 TN GEMM: C[M,N] = alpha * A[M,K] * B[N,K]^T ================
// Round-7 skeleton (tile 128x128, BK=32 halves, warp tile 64x32, mma.m16n8k16,
// 80B smem rows) with a 3-slot cp.async ring and ONE __syncthreads per k-iter.
#define BM 128
#define BN 128
#define BKH 32            // halves per k-stage
#define RSTRB 80          // bytes per smem row
#define STAGEB (BM * RSTRB)   // 10240 bytes per matrix per stage
#define NST 3

__device__ __forceinline__ void cpa16(uint32_t s, const void* g) {
    asm volatile("cp.async.cg.shared.global [%0], [%1], 16;" :: "r"(s), "l"(g));
}

// MODE 0: fp32 store; MODE 1: fp16 store; MODE 2: fp16 transposed store C[n*ldc+m]
template<int MODE>
__global__ __launch_bounds__(256)
void gemm_h(const __half* __restrict__ Ag, const __half* __restrict__ Bg, void* __restrict__ Cv,
            int K, long sA, long sB, long sC, int ldc, float alpha)
{
    __shared__ __align__(16) char As[NST][STAGEB];
    __shared__ __align__(16) char Bs[NST][STAGEB];
    const int tid = threadIdx.x, lane = tid & 31, warp = tid >> 5;
    const int m0 = blockIdx.y * BM, n0 = blockIdx.x * BN;
    const __half* A = Ag + (long)blockIdx.z * sA;
    const __half* B = Bg + (long)blockIdx.z * sB;
    const int wm = (warp & 1) * 64, wn = (warp >> 1) * 32;

    const int lr = tid >> 2;          // 0..63
    const int lcb = (tid & 3) * 16;   // byte col: 0,16,32,48

    uint32_t sA0 = (uint32_t)__cvta_generic_to_shared(&As[0][0]);
    uint32_t sB0 = (uint32_t)__cvta_generic_to_shared(&Bs[0][0]);

    float acc[4][4][4];
    #pragma unroll
    for (int i = 0; i < 4; i++)
        #pragma unroll
        for (int j = 0; j < 4; j++) { acc[i][j][0]=0.f; acc[i][j][1]=0.f; acc[i][j][2]=0.f; acc[i][j][3]=0.f; }

    const __half* aRow0 = A + (long)(m0 + lr)      * K + lcb / 2;
    const __half* aRow1 = A + (long)(m0 + lr + 64) * K + lcb / 2;
    const __half* bRow0 = B + (long)(n0 + lr)      * K + lcb / 2;
    const __half* bRow1 = B + (long)(n0 + lr + 64) * K + lcb / 2;
    uint32_t saw0 = sA0 + (uint32_t)(lr * RSTRB + lcb);
    uint32_t saw1 = sA0 + (uint32_t)((lr + 64) * RSTRB + lcb);
    uint32_t sbw0 = sB0 + (uint32_t)(lr * RSTRB + lcb);
    uint32_t sbw1 = sB0 + (uint32_t)((lr + 64) * RSTRB + lcb);

    auto issue = [&](int kt, int slot) {
        int ko = kt * BKH;
        uint32_t off = (uint32_t)slot * STAGEB;
        cpa16(saw0 + off, aRow0 + ko);
        cpa16(saw1 + off, aRow1 + ko);
        cpa16(sbw0 + off, bRow0 + ko);
        cpa16(sbw1 + off, bRow1 + ko);
        asm volatile("cp.async.commit_group;");
    };

    // ldmatrix lane address components (fp16 m16n8k16 frag recipes; validated)
    const uint32_t aoff = (uint32_t)((wm + (lane & 15)) * RSTRB + ((lane >> 4) & 1) * 16);
    const uint32_t boff = (uint32_t)((wn + (lane & 7)) * RSTRB + ((lane >> 3) & 1) * 16);

    const int KT = K >> 5;
    issue(0, 0);
    issue(1, 1);

    for (int kt = 0; kt < KT; ++kt) {
        asm volatile("cp.async.wait_group 1;");
        __syncthreads();
        if (kt + 2 < KT) issue(kt + 2, (kt + 2) % NST);
        int slot = kt % NST;
        uint32_t aBase = sA0 + (uint32_t)slot * STAGEB;
        uint32_t bBase = sB0 + (uint32_t)slot * STAGEB;
        #pragma unroll
        for (int ks = 0; ks < 2; ++ks) {
            uint32_t a[4][4], b[4][2];
            #pragma unroll
            for (int mt = 0; mt < 4; mt++) {
                uint32_t ad = aBase + aoff + (uint32_t)(mt * 16 * RSTRB + ks * 32);
                asm volatile("ldmatrix.sync.aligned.m8n8.x4.shared.b16 {%0,%1,%2,%3}, [%4];"
                    : "=r"(a[mt][0]), "=r"(a[mt][1]), "=r"(a[mt][2]), "=r"(a[mt][3]) : "r"(ad));
            }
            #pragma unroll
            for (int nt = 0; nt < 4; nt++) {
                uint32_t bd = bBase + boff + (uint32_t)(nt * 8 * RSTRB + ks * 32);
                asm volatile("ldmatrix.sync.aligned.m8n8.x2.shared.b16 {%0,%1}, [%2];"
                    : "=r"(b[nt][0]), "=r"(b[nt][1]) : "r"(bd));
            }
            #pragma unroll
            for (int mt = 0; mt < 4; mt++)
                #pragma unroll
                for (int nt = 0; nt < 4; nt++) {
                    asm volatile("mma.sync.aligned.m16n8k16.row.col.f32.f16.f16.f32 "
                        "{%0,%1,%2,%3}, {%4,%5,%6,%7}, {%8,%9}, {%0,%1,%2,%3};"
                        : "+f"(acc[mt][nt][0]), "+f"(acc[mt][nt][1]),
                          "+f"(acc[mt][nt][2]), "+f"(acc[mt][nt][3])
                        : "r"(a[mt][0]), "r"(a[mt][1]), "r"(a[mt][2]), "r"(a[mt][3]),
                          "r"(b[nt][0]), "r"(b[nt][1]));
                }
        }
    }

    // ---- epilogue ----
    const int rr = lane >> 2, cc = (lane & 3) * 2;
    #pragma unroll
    for (int mt = 0; mt < 4; mt++) {
        #pragma unroll
        for (int nt = 0; nt < 4; nt++) {
            int row = m0 + wm + mt * 16 + rr;
            int col = n0 + wn + nt * 8 + cc;
            float v0 = acc[mt][nt][0] * alpha, v1 = acc[mt][nt][1] * alpha;
            float v2 = acc[mt][nt][2] * alpha, v3 = acc[mt][nt][3] * alpha;
            if (MODE == 0) {
                float* C = (float*)Cv + (long)blockIdx.z * sC;
                *reinterpret_cast<float2*>(&C[(long)row       * ldc + col]) = make_float2(v0, v1);
                *reinterpret_cast<float2*>(&C[(long)(row + 8) * ldc + col]) = make_float2(v2, v3);
            } else if (MODE == 1) {
                __half* C = (__half*)Cv + (long)blockIdx.z * sC;
                *reinterpret_cast<__half2*>(&C[(long)row       * ldc + col]) = __floats2half2_rn(v0, v1);
                *reinterpret_cast<__half2*>(&C[(long)(row + 8) * ldc + col]) = __floats2half2_rn(v2, v3);
            } else {
                __half* C = (__half*)Cv + (long)blockIdx.z * sC;
                C[(long)col       * ldc + row    ] = __float2half_rn(v0);
                C[(long)(col + 1) * ldc + row    ] = __float2half_rn(v1);
                C[(long)col       * ldc + row + 8] = __float2half_rn(v2);
                C[(long)(col + 1) * ldc + row + 8] = __float2half_rn(v3);
            }
        }
    }
}

// ---- row softmax over 2048 fp32 cols -> fp16 P ----
__global__ void softmax_kernel(const float* __restrict__ S, __half* __restrict__ P) {
    const float* p = S + (long)blockIdx.x * SKV;
    __half* q = P + (long)blockIdx.x * SKV;
    const int tid = threadIdx.x;  // 256
    float v[8];
    float mx = -3.4e38f;
    #pragma unroll
    for (int i = 0; i < 8; i++) { v[i] = p[tid + (i << 8)]; mx = fmaxf(mx, v[i]); }
    #pragma unroll
    for (int o = 16; o; o >>= 1) mx = fmaxf(mx, __shfl_xor_sync(0xffffffffu, mx, o));
    __shared__ float red[8];
    if ((tid & 31) == 0) red[tid >> 5] = mx;
    __syncthreads();
    float m = red[0];
    #pragma unroll
    for (int i = 1; i < 8; i++) m = fmaxf(m, red[i]);
    float s = 0.f;
    #pragma unroll
    for (int i = 0; i < 8; i++) { v[i] = __expf(v[i] - m); s += v[i]; }
    #pragma unroll
    for (int o = 16; o; o >>= 1) s += __shfl_xor_sync(0xffffffffu, s, o);
    __syncthreads();
    if ((tid & 31) == 0) red[tid >> 5] = s;
    __syncthreads();
    float tot = 0.f;
    #pragma unroll
    for (int i = 0; i < 8; i++) tot += red[i];
    float inv = 1.0f / tot;
    #pragma unroll
    for (int i = 0; i < 8; i++) q[tid + (i << 8)] = __float2half_rn(v[i] * inv);
}

extern "C" void kernel_launch(void* const* d_in, const int* in_sizes, int n_in,
                              void* d_out, int out_size) {
    const float* x  = (const float*)d_in[0];
    const float* cx = (const float*)d_in[1];
    const float* wq = (const float*)d_in[2];
    const float* wk = (const float*)d_in[3];
    const float* wv = (const float*)d_in[4];
    float* out = (float*)d_out;

    __half *pXh, *pCh, *pWq, *pWk, *pWv, *pQ, *pK, *pVt, *pP;
    float *pS;
    cudaGetSymbolAddress((void**)&pXh, g_Xh);
    cudaGetSymbolAddress((void**)&pCh, g_Ch);
    cudaGetSymbolAddress((void**)&pWq, g_Wqh);
    cudaGetSymbolAddress((void**)&pWk, g_Wkh);
    cudaGetSymbolAddress((void**)&pWv, g_Wvh);
    cudaGetSymbolAddress((void**)&pQ,  g_Qh);
    cudaGetSymbolAddress((void**)&pK,  g_Kh);
    cudaGetSymbolAddress((void**)&pVt, g_Vth);
    cudaGetSymbolAddress((void**)&pS,  g_S);
    cudaGetSymbolAddress((void**)&pP,  g_P);

    // 1) convert inputs to fp16
    cvt_h_kernel<<<2048, 256>>>((const float4*)x,  (__half2*)pXh, NB * SQ * DIMD / 4);
    cvt_h_kernel<<<2048, 256>>>((const float4*)cx, (__half2*)pCh, NB * SKV * DIMD / 4);
    cvt_h_kernel<<<512,  256>>>((const float4*)wq, (__half2*)pWq, DIMD * DIMD / 4);
    cvt_h_kernel<<<512,  256>>>((const float4*)wk, (__half2*)pWk, DIMD * DIMD / 4);
    cvt_h_kernel<<<512,  256>>>((const float4*)wv, (__half2*)pWv, DIMD * DIMD / 4);

    dim3 blk(256);
    // 2) Q = X Wq^T (fp16 store)
    gemm_h<1><<<dim3(DIMD / BN, NB * SQ / BM, 1), blk>>>(
        pXh, pWq, pQ, DIMD, 0, 0, 0, DIMD, 1.f);
    // 3) K = C Wk^T
    gemm_h<1><<<dim3(DIMD / BN, NB * SKV / BM, 1), blk>>>(
        pCh, pWk, pK, DIMD, 0, 0, 0, DIMD, 1.f);
    // 4) Vt[b][e][t] = (C Wv^T)^T  (fp16 transposed store)
    gemm_h<2><<<dim3(DIMD / BN, SKV / BM, NB), blk>>>(
        pCh, pWv, pVt, DIMD, (long)SKV * DIMD, 0, (long)DIMD * SKV, SKV, 1.f);
    // 5) S[b] = Q[b] K[b]^T * D^-0.5  (fp32 store)
    gemm_h<0><<<dim3(SKV / BN, SQ / BM, NB), blk>>>(
        pQ, pK, pS, DIMD, (long)SQ * DIMD, (long)SKV * DIMD, (long)SQ * SKV, SKV, 0.03125f);
    // 6) P = softmax(S)  (fp32 -> fp16)
    softmax_kernel<<<NB * SQ, 256>>>(pS, pP);
    // 7) O[b] = P[b] Vt[b]^T  -> d_out (fp32)
    gemm_h<0><<<dim3(DIMD / BN, SQ / BM, NB), blk>>>(
        pP, pVt, out, SKV, (long)SQ * SKV, (long)DIMD * SKV, (long)SQ * DIMD, DIMD, 1.f);
}

// round 11
// speedup vs baseline: 1.5937x; 1.0795x over previous
#include <cuda_runtime.h>
#include <cuda_fp16.h>
#include <cstdint>

#define DIMD 1024
#define NB   8
#define SQ   2048
#define SKV  2048

// ---- scratch (device globals; no allocation allowed) ----
__device__ __half g_Xh[(size_t)NB * SQ * DIMD];
__device__ __half g_Ch[(size_t)NB * SKV * DIMD];
__device__ __half g_Wqh[DIMD * DIMD];
__device__ __half g_Wkh[DIMD * DIMD];
__device__ __half g_Wvh[DIMD * DIMD];
__device__ __half g_Qh[(size_t)NB * SQ * DIMD];
__device__ __half g_Kh[(size_t)NB * SKV * DIMD];
__device__ __half g_Vth[(size_t)NB * DIMD * SKV];   // [b][e][t]
__device__ float  g_S[(size_t)NB * SQ * SKV];
__device__ __half g_P[(size_t)NB * SQ * SKV];

// ---- fp32 -> fp16 conversion ----
__global__ void cvt_h_kernel(const float4* __restrict__ in, __half2* __restrict__ out, int n4) {
    int i = blockIdx.x * blockDim.x + threadIdx.x;
    int stride = gridDim.x * blockDim.x;
    for (; i < n4; i += stride) {
        float4 v = in[i];
        out[2 * i]     = __floats2half2_rn(v.x, v.y);
        out[2 * i + 1] = __floats2half2_rn(v.z, v.w);
    }
}

// ================ persistent fp16 TN GEMM ================
// Tile 128x128, BK=32 halves, warp tile 64x32, mma.m16n8k16, 80B smem rows,
// 3-slot cp.async ring, 1 syncthreads/k-iter. Persistent: CTA loops over tiles.
#define BM 128
#define BN 128
#define BKH 32
#define RSTRB 80
#define STAGEB (BM * RSTRB)
#define NST 3

__device__ __forceinline__ void cpa16(uint32_t s, const void* g) {
    asm volatile("cp.async.cg.shared.global [%0], [%1], 16;" :: "r"(s), "l"(g));
}

struct GArgs {
    const __half* A; const __half* B; void* C;
    int K; long sA, sB, sC; int ldc; float alpha;
    int ntiles, nx, nxy;
    // projection-job pointers (MODE 3)
    const __half *Xh, *Ch, *Wq, *Wk, *Wv;
    __half *Qh, *Kh, *Vt;
};

// MODE 0: generic batched TN GEMM, fp32 store.
// MODE 3: merged projections; job z: 0->Q (fp16), 1->K (fp16), 2->V (fp16 transposed).
template<int MODE>
__global__ __launch_bounds__(256)
void gemm_p(GArgs ga)
{
    __shared__ __align__(16) char As[NST][STAGEB];
    __shared__ __align__(16) char Bs[NST][STAGEB];
    const int tid = threadIdx.x, lane = tid & 31, warp = tid >> 5;
    const int wm = (warp & 1) * 64, wn = (warp >> 1) * 32;
    const int lr = tid >> 2;          // 0..63
    const int lcb = (tid & 3) * 16;   // byte col: 0,16,32,48

    uint32_t sA0 = (uint32_t)__cvta_generic_to_shared(&As[0][0]);
    uint32_t sB0 = (uint32_t)__cvta_generic_to_shared(&Bs[0][0]);
    const uint32_t saw0 = sA0 + (uint32_t)(lr * RSTRB + lcb);
    const uint32_t saw1 = sA0 + (uint32_t)((lr + 64) * RSTRB + lcb);
    const uint32_t sbw0 = sB0 + (uint32_t)(lr * RSTRB + lcb);
    const uint32_t sbw1 = sB0 + (uint32_t)((lr + 64) * RSTRB + lcb);
    const uint32_t aoff = (uint32_t)((wm + (lane & 15)) * RSTRB + ((lane >> 4) & 1) * 16);
    const uint32_t boff = (uint32_t)((wn + (lane & 7)) * RSTRB + ((lane >> 3) & 1) * 16);

    for (int t = blockIdx.x; t < ga.ntiles; t += gridDim.x) {
        // ---- decode tile ----
        const int z  = t / ga.nxy;
        const int r  = t - z * ga.nxy;
        const int my = r / ga.nx;
        const int mx = r - my * ga.nx;
        const int m0 = my * BM, n0 = mx * BN;
        const int K = ga.K;
        const __half *A, *B;
        if (MODE == 3) {
            A = (z == 0) ? ga.Xh : ga.Ch;
            B = (z == 0) ? ga.Wq : ((z == 1) ? ga.Wk : ga.Wv);
        } else {
            A = ga.A + (long)z * ga.sA;
            B = ga.B + (long)z * ga.sB;
        }

        const __half* aRow0 = A + (long)(m0 + lr)      * K + lcb / 2;
        const __half* aRow1 = A + (long)(m0 + lr + 64) * K + lcb / 2;
        const __half* bRow0 = B + (long)(n0 + lr)      * K + lcb / 2;
        const __half* bRow1 = B + (long)(n0 + lr + 64) * K + lcb / 2;

        float acc[4][4][4];
        #pragma unroll
        for (int i = 0; i < 4; i++)
            #pragma unroll
            for (int j = 0; j < 4; j++) { acc[i][j][0]=0.f; acc[i][j][1]=0.f; acc[i][j][2]=0.f; acc[i][j][3]=0.f; }

        auto issue = [&](int kt, int slot) {
            int ko = kt * BKH;
            uint32_t off = (uint32_t)slot * STAGEB;
            cpa16(saw0 + off, aRow0 + ko);
            cpa16(saw1 + off, aRow1 + ko);
            cpa16(sbw0 + off, bRow0 + ko);
            cpa16(sbw1 + off, bRow1 + ko);
            asm volatile("cp.async.commit_group;");
        };

        const int KT = K >> 5;
        issue(0, 0);
        issue(1, 1);

        for (int kt = 0; kt < KT; ++kt) {
            if (kt + 2 < KT) {
                asm volatile("cp.async.wait_group 1;");
            } else {
                asm volatile("cp.async.wait_group 0;");   // drain: closes last-group race
            }
            __syncthreads();
            if (kt + 2 < KT) issue(kt + 2, (kt + 2) % NST);
            int slot = kt % NST;
            uint32_t aBase = sA0 + (uint32_t)slot * STAGEB;
            uint32_t bBase = sB0 + (uint32_t)slot * STAGEB;
            #pragma unroll
            for (int ks = 0; ks < 2; ++ks) {
                uint32_t a[4][4], b[4][2];
                #pragma unroll
                for (int mt = 0; mt < 4; mt++) {
                    uint32_t ad = aBase + aoff + (uint32_t)(mt * 16 * RSTRB + ks * 32);
                    asm volatile("ldmatrix.sync.aligned.m8n8.x4.shared.b16 {%0,%1,%2,%3}, [%4];"
                        : "=r"(a[mt][0]), "=r"(a[mt][1]), "=r"(a[mt][2]), "=r"(a[mt][3]) : "r"(ad));
                }
                #pragma unroll
                for (int nt = 0; nt < 4; nt++) {
                    uint32_t bd = bBase + boff + (uint32_t)(nt * 8 * RSTRB + ks * 32);
                    asm volatile("ldmatrix.sync.aligned.m8n8.x2.shared.b16 {%0,%1}, [%2];"
                        : "=r"(b[nt][0]), "=r"(b[nt][1]) : "r"(bd));
                }
                #pragma unroll
                for (int mt = 0; mt < 4; mt++)
                    #pragma unroll
                    for (int nt = 0; nt < 4; nt++) {
                        asm volatile("mma.sync.aligned.m16n8k16.row.col.f32.f16.f16.f32 "
                            "{%0,%1,%2,%3}, {%4,%5,%6,%7}, {%8,%9}, {%0,%1,%2,%3};"
                            : "+f"(acc[mt][nt][0]), "+f"(acc[mt][nt][1]),
                              "+f"(acc[mt][nt][2]), "+f"(acc[mt][nt][3])
                            : "r"(a[mt][0]), "r"(a[mt][1]), "r"(a[mt][2]), "r"(a[mt][3]),
                              "r"(b[nt][0]), "r"(b[nt][1]));
                    }
            }
        }
        __syncthreads();   // all warps done with smem before next tile's prefetch

        // ---- epilogue ----
        const int rr = lane >> 2, cc = (lane & 3) * 2;
        #pragma unroll
        for (int mt = 0; mt < 4; mt++) {
            #pragma unroll
            for (int nt = 0; nt < 4; nt++) {
                int row = m0 + wm + mt * 16 + rr;
                int col = n0 + wn + nt * 8 + cc;
                float v0 = acc[mt][nt][0], v1 = acc[mt][nt][1];
                float v2 = acc[mt][nt][2], v3 = acc[mt][nt][3];
                if (MODE == 0) {
                    float a = ga.alpha;
                    v0 *= a; v1 *= a; v2 *= a; v3 *= a;
                    float* C = (float*)ga.C + (long)z * ga.sC;
                    int ldc = ga.ldc;
                    *reinterpret_cast<float2*>(&C[(long)row       * ldc + col]) = make_float2(v0, v1);
                    *reinterpret_cast<float2*>(&C[(long)(row + 8) * ldc + col]) = make_float2(v2, v3);
                } else {
                    if (z < 2) {
                        __half* C = (z == 0) ? ga.Qh : ga.Kh;
                        *reinterpret_cast<__half2*>(&C[(long)row       * DIMD + col]) = __floats2half2_rn(v0, v1);
                        *reinterpret_cast<__half2*>(&C[(long)(row + 8) * DIMD + col]) = __floats2half2_rn(v2, v3);
                    } else {
                        // V: transposed per-batch store Vt[b][e][t]
                        int b0 = row >> 11, lr0 = row & 2047;
                        int b1 = (row + 8) >> 11, lr1 = (row + 8) & 2047;
                        __half* C0 = ga.Vt + (long)b0 * DIMD * SKV;
                        __half* C1 = ga.Vt + (long)b1 * DIMD * SKV;
                        C0[(long)col       * SKV + lr0] = __float2half_rn(v0);
                        C0[(long)(col + 1) * SKV + lr0] = __float2half_rn(v1);
                        C1[(long)col       * SKV + lr1] = __float2half_rn(v2);
                        C1[(long)(col + 1) * SKV + lr1] = __float2half_rn(v3);
                    }
                }
            }
        }
    }
}

// ---- row softmax over 2048 fp32 cols -> fp16 P ----
__global__ void softmax_kernel(const float* __restrict__ S, __half* __restrict__ P) {
    const float* p = S + (long)blockIdx.x * SKV;
    __half* q = P + (long)blockIdx.x * SKV;
    const int tid = threadIdx.x;  // 256
    float v[8];
    float mx = -3.4e38f;
    #pragma unroll
    for (int i = 0; i < 8; i++) { v[i] = p[tid + (i << 8)]; mx = fmaxf(mx, v[i]); }
    #pragma unroll
    for (int o = 16; o; o >>= 1) mx = fmaxf(mx, __shfl_xor_sync(0xffffffffu, mx, o));
    __shared__ float red[8];
    if ((tid & 31) == 0) red[tid >> 5] = mx;
    __syncthreads();
    float m = red[0];
    #pragma unroll
    for (int i = 1; i < 8; i++) m = fmaxf(m, red[i]);
    float s = 0.f;
    #pragma unroll
    for (int i = 0; i < 8; i++) { v[i] = __expf(v[i] - m); s += v[i]; }
    #pragma unroll
    for (int o = 16; o; o >>= 1) s += __shfl_xor_sync(0xffffffffu, s, o);
    __syncthreads();
    if ((tid & 31) == 0) red[tid >> 5] = s;
    __syncthreads();
    float tot = 0.f;
    #pragma unroll
    for (int i = 0; i < 8; i++) tot += red[i];
    float inv = 1.0f / tot;
    #pragma unroll
    for (int i = 0; i < 8; i++) q[tid + (i << 8)] = __float2half_rn(v[i] * inv);
}

extern "C" void kernel_launch(void* const* d_in, const int* in_sizes, int n_in,
                              void* d_out, int out_size) {
    const float* x  = (const float*)d_in[0];
    const float* cx = (const float*)d_in[1];
    const float* wq = (const float*)d_in[2];
    const float* wk = (const float*)d_in[3];
    const float* wv = (const float*)d_in[4];
    float* out = (float*)d_out;

    __half *pXh, *pCh, *pWq, *pWk, *pWv, *pQ, *pK, *pVt, *pP;
    float *pS;
    cudaGetSymbolAddress((void**)&pXh, g_Xh);
    cudaGetSymbolAddress((void**)&pCh, g_Ch);
    cudaGetSymbolAddress((void**)&pWq, g_Wqh);
    cudaGetSymbolAddress((void**)&pWk, g_Wkh);
    cudaGetSymbolAddress((void**)&pWv, g_Wvh);
    cudaGetSymbolAddress((void**)&pQ,  g_Qh);
    cudaGetSymbolAddress((void**)&pK,  g_Kh);
    cudaGetSymbolAddress((void**)&pVt, g_Vth);
    cudaGetSymbolAddress((void**)&pS,  g_S);
    cudaGetSymbolAddress((void**)&pP,  g_P);

    // persistent grid size = SMs * resident CTAs per SM
    int nsm = 148, occ0 = 1, occ3 = 1;
    cudaDeviceGetAttribute(&nsm, cudaDevAttrMultiProcessorCount, 0);
    cudaOccupancyMaxActiveBlocksPerMultiprocessor(&occ0, gemm_p<0>, 256, 0);
    cudaOccupancyMaxActiveBlocksPerMultiprocessor(&occ3, gemm_p<3>, 256, 0);
    if (occ0 < 1) occ0 = 1;
    if (occ3 < 1) occ3 = 1;
    const int grid0 = nsm * occ0, grid3 = nsm * occ3;

    // 1) convert inputs to fp16
    cvt_h_kernel<<<2048, 256>>>((const float4*)x,  (__half2*)pXh, NB * SQ * DIMD / 4);
    cvt_h_kernel<<<2048, 256>>>((const float4*)cx, (__half2*)pCh, NB * SKV * DIMD / 4);
    cvt_h_kernel<<<512,  256>>>((const float4*)wq, (__half2*)pWq, DIMD * DIMD / 4);
    cvt_h_kernel<<<512,  256>>>((const float4*)wk, (__half2*)pWk, DIMD * DIMD / 4);
    cvt_h_kernel<<<512,  256>>>((const float4*)wv, (__half2*)pWv, DIMD * DIMD / 4);

    GArgs ga{};
    ga.Xh = pXh; ga.Ch = pCh; ga.Wq = pWq; ga.Wk = pWk; ga.Wv = pWv;
    ga.Qh = pQ;  ga.Kh = pK;  ga.Vt = pVt;

    // 2) merged projections: Q, K, V(transposed). tiles: 3 jobs x 128 m x 8 n
    {
        GArgs a = ga;
        a.K = DIMD; a.ntiles = 3 * 128 * 8; a.nx = 8; a.nxy = 128 * 8;
        int g = grid3 < a.ntiles ? grid3 : a.ntiles;
        gemm_p<3><<<g, 256>>>(a);
    }
    // 3) S[b] = Q[b] K[b]^T * D^-0.5 (fp32). tiles: 8 b x 16 m x 16 n
    {
        GArgs a = ga;
        a.A = pQ; a.B = pK; a.C = pS;
        a.K = DIMD; a.sA = (long)SQ * DIMD; a.sB = (long)SKV * DIMD; a.sC = (long)SQ * SKV;
        a.ldc = SKV; a.alpha = 0.03125f;
        a.ntiles = NB * 16 * 16; a.nx = 16; a.nxy = 16 * 16;
        int g = grid0 < a.ntiles ? grid0 : a.ntiles;
        gemm_p<0><<<g, 256>>>(a);
    }
    // 4) P = softmax(S) (fp32 -> fp16)
    softmax_kernel<<<NB * SQ, 256>>>(pS, pP);
    // 5) O[b] = P[b] Vt[b]^T -> d_out (fp32). tiles: 8 b x 16 m x 8 n  (nx = DIMD/BN = 8)
    {
        GArgs a = ga;
        a.A = pP; a.B = pVt; a.C = out;
        a.K = SKV; a.sA = (long)SQ * SKV; a.sB = (long)DIMD * SKV; a.sC = (long)SQ * DIMD;
        a.ldc = DIMD; a.alpha = 1.f;
        a.ntiles = NB * 16 * 8; a.nx = 8; a.nxy = 16 * 8;
        int g = grid0 < a.ntiles ? grid0 : a.ntiles;
        gemm_p<0><<<g, 256>>>(a);
    }
}

// round 12
// speedup vs baseline: 1.6371x; 1.0272x over previous
#include <cuda_runtime.h>
#include <cuda_fp16.h>
#include <cstdint>

#define DIMD 1024
#define NB   8
#define SQ   2048
#define SKV  2048

// ---- scratch (device globals; no allocation allowed) ----
__device__ __half g_Xh[(size_t)NB * SQ * DIMD];
__device__ __half g_Ch[(size_t)NB * SKV * DIMD];
__device__ __half g_Wqh[DIMD * DIMD];
__device__ __half g_Wkh[DIMD * DIMD];
__device__ __half g_Wvh[DIMD * DIMD];
__device__ __half g_Qh[(size_t)NB * SQ * DIMD];
__device__ __half g_Kh[(size_t)NB * SKV * DIMD];
__device__ __half g_Vth[(size_t)NB * DIMD * SKV];   // [b][e][t]
__device__ __half g_E[(size_t)NB * SQ * SKV];       // exp(alpha*S), fp16
__device__ float  g_den[(size_t)NB * SQ];           // per-row sum of exp

// ---- merged fp32 -> fp16 conversion over 5 arrays ----
struct CvtArgs {
    const float4* src[5];
    __half2* dst[5];
    int n4[5];
    int tot;
};
__global__ void cvt_all_kernel(CvtArgs a) {
    int stride = gridDim.x * blockDim.x;
    for (int i = blockIdx.x * blockDim.x + threadIdx.x; i < a.tot; i += stride) {
        int j = i, s = 0;
        while (s < 4 && j >= a.n4[s]) { j -= a.n4[s]; s++; }
        float4 v = a.src[s][j];
        a.dst[s][2 * j]     = __floats2half2_rn(v.x, v.y);
        a.dst[s][2 * j + 1] = __floats2half2_rn(v.z, v.w);
    }
}

// ================ persistent fp16 TN GEMM ================
// Tile 128x128, BK=32 halves, warp tile 64x32, mma.m16n8k16, 80B smem rows,
// 3-slot cp.async ring, 1 syncthreads/k-iter. Persistent: CTA loops over tiles.
#define BM 128
#define BN 128
#define BKH 32
#define RSTRB 80
#define STAGEB (BM * RSTRB)
#define NST 3

__device__ __forceinline__ void cpa16(uint32_t s, const void* g) {
    asm volatile("cp.async.cg.shared.global [%0], [%1], 16;" :: "r"(s), "l"(g));
}

struct GArgs {
    const __half* A; const __half* B; void* C;
    int K; long sA, sB, sC; int ldc;
    int ntiles, nx, nxy;
    // projection-job pointers (MODE 3)
    const __half *Xh, *Ch, *Wq, *Wk, *Wv;
    __half *Qh, *Kh, *Vt;
    // attention extras
    __half* Eh;     // MODE 4 output
    float*  den;    // MODE 4 accumulate, MODE 5 read
};

// MODE 3: merged projections; job z: 0->Q (fp16), 1->K (fp16), 2->V (fp16 transposed).
// MODE 4: S-GEMM -> E = exp(alpha*acc) fp16, + row-sum atomics into den.
// MODE 5: O-GEMM (A=E fp16), epilogue scales row r by 1/den[r], fp32 store.
template<int MODE>
__global__ __launch_bounds__(256)
void gemm_p(GArgs ga)
{
    __shared__ __align__(16) char As[NST][STAGEB];
    __shared__ __align__(16) char Bs[NST][STAGEB];
    const int tid = threadIdx.x, lane = tid & 31, warp = tid >> 5;
    const int wm = (warp & 1) * 64, wn = (warp >> 1) * 32;
    const int lr = tid >> 2;          // 0..63
    const int lcb = (tid & 3) * 16;   // byte col: 0,16,32,48

    uint32_t sA0 = (uint32_t)__cvta_generic_to_shared(&As[0][0]);
    uint32_t sB0 = (uint32_t)__cvta_generic_to_shared(&Bs[0][0]);
    const uint32_t saw0 = sA0 + (uint32_t)(lr * RSTRB + lcb);
    const uint32_t saw1 = sA0 + (uint32_t)((lr + 64) * RSTRB + lcb);
    const uint32_t sbw0 = sB0 + (uint32_t)(lr * RSTRB + lcb);
    const uint32_t sbw1 = sB0 + (uint32_t)((lr + 64) * RSTRB + lcb);
    const uint32_t aoff = (uint32_t)((wm + (lane & 15)) * RSTRB + ((lane >> 4) & 1) * 16);
    const uint32_t boff = (uint32_t)((wn + (lane & 7)) * RSTRB + ((lane >> 3) & 1) * 16);

    for (int t = blockIdx.x; t < ga.ntiles; t += gridDim.x) {
        // ---- decode tile ----
        const int z  = t / ga.nxy;
        const int r  = t - z * ga.nxy;
        const int my = r / ga.nx;
        const int mx = r - my * ga.nx;
        const int m0 = my * BM, n0 = mx * BN;
        const int K = ga.K;
        const __half *A, *B;
        if (MODE == 3) {
            A = (z == 0) ? ga.Xh : ga.Ch;
            B = (z == 0) ? ga.Wq : ((z == 1) ? ga.Wk : ga.Wv);
        } else {
            A = ga.A + (long)z * ga.sA;
            B = ga.B + (long)z * ga.sB;
        }

        const __half* aRow0 = A + (long)(m0 + lr)      * K + lcb / 2;
        const __half* aRow1 = A + (long)(m0 + lr + 64) * K + lcb / 2;
        const __half* bRow0 = B + (long)(n0 + lr)      * K + lcb / 2;
        const __half* bRow1 = B + (long)(n0 + lr + 64) * K + lcb / 2;

        float acc[4][4][4];
        #pragma unroll
        for (int i = 0; i < 4; i++)
            #pragma unroll
            for (int j = 0; j < 4; j++) { acc[i][j][0]=0.f; acc[i][j][1]=0.f; acc[i][j][2]=0.f; acc[i][j][3]=0.f; }

        auto issue = [&](int kt, int slot) {
            int ko = kt * BKH;
            uint32_t off = (uint32_t)slot * STAGEB;
            cpa16(saw0 + off, aRow0 + ko);
            cpa16(saw1 + off, aRow1 + ko);
            cpa16(sbw0 + off, bRow0 + ko);
            cpa16(sbw1 + off, bRow1 + ko);
            asm volatile("cp.async.commit_group;");
        };

        const int KT = K >> 5;
        issue(0, 0);
        issue(1, 1);

        for (int kt = 0; kt < KT; ++kt) {
            if (kt + 2 < KT) {
                asm volatile("cp.async.wait_group 1;");
            } else {
                asm volatile("cp.async.wait_group 0;");
            }
            __syncthreads();
            if (kt + 2 < KT) issue(kt + 2, (kt + 2) % NST);
            int slot = kt % NST;
            uint32_t aBase = sA0 + (uint32_t)slot * STAGEB;
            uint32_t bBase = sB0 + (uint32_t)slot * STAGEB;
            #pragma unroll
            for (int ks = 0; ks < 2; ++ks) {
                uint32_t a[4][4], b[4][2];
                #pragma unroll
                for (int mt = 0; mt < 4; mt++) {
                    uint32_t ad = aBase + aoff + (uint32_t)(mt * 16 * RSTRB + ks * 32);
                    asm volatile("ldmatrix.sync.aligned.m8n8.x4.shared.b16 {%0,%1,%2,%3}, [%4];"
                        : "=r"(a[mt][0]), "=r"(a[mt][1]), "=r"(a[mt][2]), "=r"(a[mt][3]) : "r"(ad));
                }
                #pragma unroll
                for (int nt = 0; nt < 4; nt++) {
                    uint32_t bd = bBase + boff + (uint32_t)(nt * 8 * RSTRB + ks * 32);
                    asm volatile("ldmatrix.sync.aligned.m8n8.x2.shared.b16 {%0,%1}, [%2];"
                        : "=r"(b[nt][0]), "=r"(b[nt][1]) : "r"(bd));
                }
                #pragma unroll
                for (int mt = 0; mt < 4; mt++)
                    #pragma unroll
                    for (int nt = 0; nt < 4; nt++) {
                        asm volatile("mma.sync.aligned.m16n8k16.row.col.f32.f16.f16.f32 "
                            "{%0,%1,%2,%3}, {%4,%5,%6,%7}, {%8,%9}, {%0,%1,%2,%3};"
                            : "+f"(acc[mt][nt][0]), "+f"(acc[mt][nt][1]),
                              "+f"(acc[mt][nt][2]), "+f"(acc[mt][nt][3])
                            : "r"(a[mt][0]), "r"(a[mt][1]), "r"(a[mt][2]), "r"(a[mt][3]),
                              "r"(b[nt][0]), "r"(b[nt][1]));
                    }
            }
        }
        __syncthreads();   // all warps done with smem before next tile's prefetch

        // ---- epilogue ----
        const int rr = lane >> 2, cc = (lane & 3) * 2;
        if (MODE == 3) {
            #pragma unroll
            for (int mt = 0; mt < 4; mt++) {
                #pragma unroll
                for (int nt = 0; nt < 4; nt++) {
                    int row = m0 + wm + mt * 16 + rr;
                    int col = n0 + wn + nt * 8 + cc;
                    float v0 = acc[mt][nt][0], v1 = acc[mt][nt][1];
                    float v2 = acc[mt][nt][2], v3 = acc[mt][nt][3];
                    if (z < 2) {
                        __half* C = (z == 0) ? ga.Qh : ga.Kh;
                        *reinterpret_cast<__half2*>(&C[(long)row       * DIMD + col]) = __floats2half2_rn(v0, v1);
                        *reinterpret_cast<__half2*>(&C[(long)(row + 8) * DIMD + col]) = __floats2half2_rn(v2, v3);
                    } else {
                        int b0 = row >> 11, lr0 = row & 2047;
                        int b1 = (row + 8) >> 11, lr1 = (row + 8) & 2047;
                        __half* C0 = ga.Vt + (long)b0 * DIMD * SKV;
                        __half* C1 = ga.Vt + (long)b1 * DIMD * SKV;
                        C0[(long)col       * SKV + lr0] = __float2half_rn(v0);
                        C0[(long)(col + 1) * SKV + lr0] = __float2half_rn(v1);
                        C1[(long)col       * SKV + lr1] = __float2half_rn(v2);
                        C1[(long)(col + 1) * SKV + lr1] = __float2half_rn(v3);
                    }
                }
            }
        } else if (MODE == 4) {
            __half* E  = ga.Eh  + (long)z * SQ * SKV;
            float* den = ga.den + (long)z * SQ;
            const float C = 0.03125f;   // alpha; exp(alpha*acc)
            #pragma unroll
            for (int mt = 0; mt < 4; mt++) {
                int row = m0 + wm + mt * 16 + rr;
                float rs0 = 0.f, rs1 = 0.f;
                #pragma unroll
                for (int nt = 0; nt < 4; nt++) {
                    int col = n0 + wn + nt * 8 + cc;
                    float e0 = __expf(acc[mt][nt][0] * C);
                    float e1 = __expf(acc[mt][nt][1] * C);
                    float e2 = __expf(acc[mt][nt][2] * C);
                    float e3 = __expf(acc[mt][nt][3] * C);
                    *reinterpret_cast<__half2*>(&E[(long)row       * SKV + col]) = __floats2half2_rn(e0, e1);
                    *reinterpret_cast<__half2*>(&E[(long)(row + 8) * SKV + col]) = __floats2half2_rn(e2, e3);
                    rs0 += e0 + e1;
                    rs1 += e2 + e3;
                }
                rs0 += __shfl_xor_sync(0xffffffffu, rs0, 1);
                rs0 += __shfl_xor_sync(0xffffffffu, rs0, 2);
                rs1 += __shfl_xor_sync(0xffffffffu, rs1, 1);
                rs1 += __shfl_xor_sync(0xffffffffu, rs1, 2);
                if ((lane & 3) == 0) {
                    atomicAdd(&den[row],     rs0);
                    atomicAdd(&den[row + 8], rs1);
                }
            }
        } else {  // MODE 5
            float* C = (float*)ga.C + (long)z * ga.sC;
            const float* den = ga.den + (long)z * SQ;
            int ldc = ga.ldc;
            #pragma unroll
            for (int mt = 0; mt < 4; mt++) {
                int row = m0 + wm + mt * 16 + rr;
                float i0 = 1.0f / den[row];
                float i1 = 1.0f / den[row + 8];
                #pragma unroll
                for (int nt = 0; nt < 4; nt++) {
                    int col = n0 + wn + nt * 8 + cc;
                    float v0 = acc[mt][nt][0] * i0, v1 = acc[mt][nt][1] * i0;
                    float v2 = acc[mt][nt][2] * i1, v3 = acc[mt][nt][3] * i1;
                    *reinterpret_cast<float2*>(&C[(long)row       * ldc + col]) = make_float2(v0, v1);
                    *reinterpret_cast<float2*>(&C[(long)(row + 8) * ldc + col]) = make_float2(v2, v3);
                }
            }
        }
    }
}

extern "C" void kernel_launch(void* const* d_in, const int* in_sizes, int n_in,
                              void* d_out, int out_size) {
    const float* x  = (const float*)d_in[0];
    const float* cx = (const float*)d_in[1];
    const float* wq = (const float*)d_in[2];
    const float* wk = (const float*)d_in[3];
    const float* wv = (const float*)d_in[4];
    float* out = (float*)d_out;

    __half *pXh, *pCh, *pWq, *pWk, *pWv, *pQ, *pK, *pVt, *pE;
    float *pDen;
    cudaGetSymbolAddress((void**)&pXh, g_Xh);
    cudaGetSymbolAddress((void**)&pCh, g_Ch);
    cudaGetSymbolAddress((void**)&pWq, g_Wqh);
    cudaGetSymbolAddress((void**)&pWk, g_Wkh);
    cudaGetSymbolAddress((void**)&pWv, g_Wvh);
    cudaGetSymbolAddress((void**)&pQ,  g_Qh);
    cudaGetSymbolAddress((void**)&pK,  g_Kh);
    cudaGetSymbolAddress((void**)&pVt, g_Vth);
    cudaGetSymbolAddress((void**)&pE,  g_E);
    cudaGetSymbolAddress((void**)&pDen, g_den);

    int nsm = 148, occ3 = 1, occ4 = 1, occ5 = 1;
    cudaDeviceGetAttribute(&nsm, cudaDevAttrMultiProcessorCount, 0);
    cudaOccupancyMaxActiveBlocksPerMultiprocessor(&occ3, gemm_p<3>, 256, 0);
    cudaOccupancyMaxActiveBlocksPerMultiprocessor(&occ4, gemm_p<4>, 256, 0);
    cudaOccupancyMaxActiveBlocksPerMultiprocessor(&occ5, gemm_p<5>, 256, 0);
    if (occ3 < 1) occ3 = 1;
    if (occ4 < 1) occ4 = 1;
    if (occ5 < 1) occ5 = 1;

    // 0) zero denominators (graph-capturable async memset)
    cudaMemsetAsync(pDen, 0, (size_t)NB * SQ * sizeof(float));

    // 1) convert all inputs to fp16 in one launch
    {
        CvtArgs ca{};
        ca.src[0] = (const float4*)x;  ca.dst[0] = (__half2*)pXh; ca.n4[0] = NB * SQ * DIMD / 4;
        ca.src[1] = (const float4*)cx; ca.dst[1] = (__half2*)pCh; ca.n4[1] = NB * SKV * DIMD / 4;
        ca.src[2] = (const float4*)wq; ca.dst[2] = (__half2*)pWq; ca.n4[2] = DIMD * DIMD / 4;
        ca.src[3] = (const float4*)wk; ca.dst[3] = (__half2*)pWk; ca.n4[3] = DIMD * DIMD / 4;
        ca.src[4] = (const float4*)wv; ca.dst[4] = (__half2*)pWv; ca.n4[4] = DIMD * DIMD / 4;
        ca.tot = ca.n4[0] + ca.n4[1] + ca.n4[2] + ca.n4[3] + ca.n4[4];
        cvt_all_kernel<<<nsm * 8, 256>>>(ca);
    }

    GArgs ga{};
    ga.Xh = pXh; ga.Ch = pCh; ga.Wq = pWq; ga.Wk = pWk; ga.Wv = pWv;
    ga.Qh = pQ;  ga.Kh = pK;  ga.Vt = pVt;
    ga.Eh = pE;  ga.den = pDen;

    // 2) merged projections: Q, K, V(transposed). tiles: 3 jobs x 128 m x 8 n
    {
        GArgs a = ga;
        a.K = DIMD; a.ntiles = 3 * 128 * 8; a.nx = 8; a.nxy = 128 * 8;
        int g = nsm * occ3; if (g > a.ntiles) g = a.ntiles;
        gemm_p<3><<<g, 256>>>(a);
    }
    // 3) E[b] = exp(alpha * Q[b] K[b]^T), den[b] += row sums. tiles: 8 b x 16 m x 16 n
    {
        GArgs a = ga;
        a.A = pQ; a.B = pK;
        a.K = DIMD; a.sA = (long)SQ * DIMD; a.sB = (long)SKV * DIMD;
        a.ntiles = NB * 16 * 16; a.nx = 16; a.nxy = 16 * 16;
        int g = nsm * occ4; if (g > a.ntiles) g = a.ntiles;
        gemm_p<4><<<g, 256>>>(a);
    }
    // 4) O[b] = (E[b] Vt[b]^T) / den -> d_out (fp32). tiles: 8 b x 16 m x 8 n
    {
        GArgs a = ga;
        a.A = pE; a.B = pVt; a.C = out;
        a.K = SKV; a.sA = (long)SQ * SKV; a.sB = (long)DIMD * SKV; a.sC = (long)SQ * DIMD;
        a.ldc = DIMD;
        a.ntiles = NB * 16 * 8; a.nx = 8; a.nxy = 16 * 8;
        int g = nsm * occ5; if (g > a.ntiles) g = a.ntiles;
        gemm_p<5><<<g, 256>>>(a);
    }
}